// round 4
// baseline (speedup 1.0000x reference)
#include <cuda_runtime.h>
#include <math.h>

#define NB 4
#define C 256
#define L 4096   // 64*64

// ---------------- scratch (__device__ globals: sanctioned alloc-free scratch) ----
__device__ float g_Qt[(size_t)NB * L * C];   // (n, i, c)  16.8 MB
__device__ float g_Kt[(size_t)NB * L * C];
__device__ float g_Vt[(size_t)NB * L * C];
__device__ float g_S [(size_t)NB * L * L];   // raw logits (n, i, j)  268 MB
__device__ float g_M [NB * L];               // row max
__device__ float g_Z [NB * L];               // row sum of exp(s - m)

// 8x8 micro-tile inner product over the 8-deep smem k-chunk
#define GEMM_INNER()                                                      \
    _Pragma("unroll")                                                     \
    for (int kk = 0; kk < 8; kk++) {                                      \
        float a[8], b[8];                                                 \
        *(float4*)&a[0] = *(const float4*)&As[kk][tm * 8];                \
        *(float4*)&a[4] = *(const float4*)&As[kk][tm * 8 + 4];            \
        *(float4*)&b[0] = *(const float4*)&Bs[kk][tn * 8];                \
        *(float4*)&b[4] = *(const float4*)&Bs[kk][tn * 8 + 4];            \
        _Pragma("unroll")                                                 \
        for (int di = 0; di < 8; di++)                                    \
            _Pragma("unroll")                                             \
            for (int dj = 0; dj < 8; dj++)                                \
                acc[di][dj] = fmaf(a[di], b[dj], acc[di][dj]);            \
    }

// ---------------------------------------------------------------------------
// Kernel 1: 1x1 conv (channel-mixing GEMM). grid.z = nb*3 + which.
// Out[i][o] = sum_c W[o][c] * x[n][c][i] + b[o], written (i, o) row-major.
// m-side = i (128), n-side = o (128), k = c (chunks of 8).
// ---------------------------------------------------------------------------
__global__ __launch_bounds__(256) void conv1x1_kernel(
    const float* __restrict__ x,
    const float* __restrict__ Wq, const float* __restrict__ bq,
    const float* __restrict__ Wk, const float* __restrict__ bk,
    const float* __restrict__ Wv, const float* __restrict__ bv)
{
    int which = blockIdx.z % 3;
    int nb    = blockIdx.z / 3;
    const float* W    = (which == 0) ? Wq : (which == 1) ? Wk : Wv;
    const float* bias = (which == 0) ? bq : (which == 1) ? bk : bv;
    float* Out = ((which == 0) ? g_Qt : (which == 1) ? g_Kt : g_Vt)
                 + (size_t)nb * L * C;
    const float* xb = x + (size_t)nb * C * L;

    int o0 = blockIdx.x * 128;   // 2 tiles over C
    int i0 = blockIdx.y * 128;   // 32 tiles over L

    __shared__ float As[8][128];  // [c][i]
    __shared__ float Bs[8][128];  // [c][o]

    int t  = threadIdx.x;
    int tm = t >> 4, tn = t & 15;

    // As load mapping (x is c-major, i contiguous -> natural copy)
    int arow = t >> 5;            // c in chunk (0..7)
    int acol = (t & 31) * 4;      // i
    // Bs load mapping (W is o-major, c contiguous -> transpose on store)
    int brow = t >> 1;            // o (0..127)
    int bcol = (t & 1) * 4;       // c in chunk

    float acc[8][8] = {};

    float4 av = *(const float4*)&xb[(size_t)arow * L + i0 + acol];
    float4 bw = *(const float4*)&W[(size_t)(o0 + brow) * C + bcol];

    for (int kc = 0; kc < C; kc += 8) {
        __syncthreads();
        *(float4*)&As[arow][acol] = av;
        Bs[bcol + 0][brow] = bw.x;
        Bs[bcol + 1][brow] = bw.y;
        Bs[bcol + 2][brow] = bw.z;
        Bs[bcol + 3][brow] = bw.w;
        __syncthreads();
        if (kc + 8 < C) {
            av = *(const float4*)&xb[(size_t)(kc + 8 + arow) * L + i0 + acol];
            bw = *(const float4*)&W[(size_t)(o0 + brow) * C + kc + 8 + bcol];
        }
        GEMM_INNER();
    }

    #pragma unroll
    for (int di = 0; di < 8; di++) {
        int i = i0 + tm * 8 + di;
        #pragma unroll
        for (int dj = 0; dj < 8; dj += 4) {
            int o = o0 + tn * 8 + dj;
            float4 v;
            v.x = acc[di][dj + 0] + bias[o + 0];
            v.y = acc[di][dj + 1] + bias[o + 1];
            v.z = acc[di][dj + 2] + bias[o + 2];
            v.w = acc[di][dj + 3] + bias[o + 3];
            *(float4*)&Out[(size_t)i * C + o] = v;
        }
    }
}

// ---------------------------------------------------------------------------
// Kernel 2: S[i][j] = sum_c Q[i][c] * K[j][c]  (raw logits to global scratch)
// m = i, n = j, k = c. Both operands are (row, c) with c contiguous ->
// transpose-on-store for both tiles.
// ---------------------------------------------------------------------------
__global__ __launch_bounds__(256) void qk_kernel()
{
    int nb = blockIdx.z;
    int j0 = blockIdx.x * 128;
    int i0 = blockIdx.y * 128;
    const float* Q  = g_Qt + (size_t)nb * L * C;
    const float* Kt = g_Kt + (size_t)nb * L * C;

    __shared__ float As[8][128];  // [c][i]
    __shared__ float Bs[8][128];  // [c][j]

    int t  = threadIdx.x;
    int tm = t >> 4, tn = t & 15;
    int lrow = t >> 1;            // 0..127
    int lc   = (t & 1) * 4;       // 0 or 4

    float acc[8][8] = {};

    float4 qa = *(const float4*)&Q [(size_t)(i0 + lrow) * C + lc];
    float4 kb = *(const float4*)&Kt[(size_t)(j0 + lrow) * C + lc];

    for (int kc = 0; kc < C; kc += 8) {
        __syncthreads();
        As[lc + 0][lrow] = qa.x; As[lc + 1][lrow] = qa.y;
        As[lc + 2][lrow] = qa.z; As[lc + 3][lrow] = qa.w;
        Bs[lc + 0][lrow] = kb.x; Bs[lc + 1][lrow] = kb.y;
        Bs[lc + 2][lrow] = kb.z; Bs[lc + 3][lrow] = kb.w;
        __syncthreads();
        if (kc + 8 < C) {
            qa = *(const float4*)&Q [(size_t)(i0 + lrow) * C + kc + 8 + lc];
            kb = *(const float4*)&Kt[(size_t)(j0 + lrow) * C + kc + 8 + lc];
        }
        GEMM_INNER();
    }

    float* Sp = g_S + (size_t)nb * L * L;
    #pragma unroll
    for (int di = 0; di < 8; di++) {
        size_t ro = (size_t)(i0 + tm * 8 + di) * L + j0 + tn * 8;
        *(float4*)&Sp[ro]     = make_float4(acc[di][0], acc[di][1], acc[di][2], acc[di][3]);
        *(float4*)&Sp[ro + 4] = make_float4(acc[di][4], acc[di][5], acc[di][6], acc[di][7]);
    }
}

// ---------------------------------------------------------------------------
// Kernel 3: per-row max and sum of exp(s - max). One block per (row, batch).
// ---------------------------------------------------------------------------
__global__ __launch_bounds__(256) void stats_kernel()
{
    int i  = blockIdx.x;
    int nb = blockIdx.y;
    const float* row = g_S + (size_t)nb * L * L + (size_t)i * L;
    __shared__ float red[256];
    int t = threadIdx.x;

    float vals[16];
    float m = -3.4e38f;
    #pragma unroll
    for (int r = 0; r < 16; r++) {
        vals[r] = row[t + r * 256];
        m = fmaxf(m, vals[r]);
    }
    red[t] = m;
    __syncthreads();
    for (int s = 128; s > 0; s >>= 1) {
        if (t < s) red[t] = fmaxf(red[t], red[t + s]);
        __syncthreads();
    }
    m = red[0];
    __syncthreads();

    float z = 0.0f;
    #pragma unroll
    for (int r = 0; r < 16; r++) z += __expf(vals[r] - m);
    red[t] = z;
    __syncthreads();
    for (int s = 128; s > 0; s >>= 1) {
        if (t < s) red[t] += red[t + s];
        __syncthreads();
    }
    if (t == 0) { g_M[nb * L + i] = m; g_Z[nb * L + i] = red[0]; }
}

// ---------------------------------------------------------------------------
// Kernel 4: att[c][i] = sum_j exp(S[i][j]-m_i) * V[j][c];
//           out[n][c][i] = x + gamma * att / Z_i
// m-side = c (128, 2 tiles), n-side = i (128, 32 tiles), k = j (4096, chunks of 8).
// exp applied once at smem-store of the P tile. Output coalesced along i.
// ---------------------------------------------------------------------------
__global__ __launch_bounds__(256) void av_kernel(
    const float* __restrict__ x, float* __restrict__ out,
    const float* __restrict__ gamma_p)
{
    int nb = blockIdx.z;
    int i0 = blockIdx.x * 128;   // 32 tiles
    int c0 = blockIdx.y * 128;   // 2 tiles
    const float* Sp = g_S  + (size_t)nb * L * L;
    const float* V  = g_Vt + (size_t)nb * L * C;

    __shared__ float As[8][128];  // [j][c]   (V, natural layout)
    __shared__ float Bs[8][128];  // [j][i]   (P = exp(S-m), transpose on store)
    __shared__ float Ms[128];
    __shared__ float Zs[128];

    int t  = threadIdx.x;
    int tm = t >> 4, tn = t & 15;
    int lrow = t >> 1;            // i local
    int lc   = (t & 1) * 4;       // j in chunk
    int arow = t >> 5;            // j in chunk (0..7)
    int acol = (t & 31) * 4;      // c

    if (t < 128) {
        Ms[t] = g_M[nb * L + i0 + t];
        Zs[t] = g_Z[nb * L + i0 + t];
    }
    __syncthreads();
    float mrow = Ms[lrow];

    float acc[8][8] = {};

    float4 pa = *(const float4*)&Sp[(size_t)(i0 + lrow) * L + lc];
    float4 va = *(const float4*)&V [(size_t)arow * C + c0 + acol];

    for (int jk = 0; jk < L; jk += 8) {
        __syncthreads();
        *(float4*)&As[arow][acol] = va;
        Bs[lc + 0][lrow] = __expf(pa.x - mrow);
        Bs[lc + 1][lrow] = __expf(pa.y - mrow);
        Bs[lc + 2][lrow] = __expf(pa.z - mrow);
        Bs[lc + 3][lrow] = __expf(pa.w - mrow);
        __syncthreads();
        if (jk + 8 < L) {
            pa = *(const float4*)&Sp[(size_t)(i0 + lrow) * L + jk + 8 + lc];
            va = *(const float4*)&V [(size_t)(jk + 8 + arow) * C + c0 + acol];
        }
        GEMM_INNER();
    }

    float gamma = gamma_p[0];
    float zinv[8];
    #pragma unroll
    for (int dj = 0; dj < 8; dj++) zinv[dj] = gamma / Zs[tn * 8 + dj];

    #pragma unroll
    for (int di = 0; di < 8; di++) {
        int c = c0 + tm * 8 + di;
        size_t ro = ((size_t)nb * C + c) * L + i0 + tn * 8;
        #pragma unroll
        for (int dj = 0; dj < 8; dj += 4) {
            float4 xv = *(const float4*)&x[ro + dj];
            float4 ov;
            ov.x = xv.x + acc[di][dj + 0] * zinv[dj + 0];
            ov.y = xv.y + acc[di][dj + 1] * zinv[dj + 1];
            ov.z = xv.z + acc[di][dj + 2] * zinv[dj + 2];
            ov.w = xv.w + acc[di][dj + 3] * zinv[dj + 3];
            *(float4*)&out[ro + dj] = ov;
        }
    }
}

// ---------------------------------------------------------------------------
extern "C" void kernel_launch(void* const* d_in, const int* in_sizes, int n_in,
                              void* d_out, int out_size)
{
    const float* x     = (const float*)d_in[0];
    const float* Wq    = (const float*)d_in[1];
    const float* bq    = (const float*)d_in[2];
    const float* Wk    = (const float*)d_in[3];
    const float* bk    = (const float*)d_in[4];
    const float* Wv    = (const float*)d_in[5];
    const float* bv    = (const float*)d_in[6];
    const float* gamma = (const float*)d_in[7];
    float* out = (float*)d_out;

    dim3 blk(256);
    // QKV projections: (o_tiles=2, i_tiles=32, nb*3=12)
    conv1x1_kernel<<<dim3(2, 32, NB * 3), blk>>>(x, Wq, bq, Wk, bk, Wv, bv);
    // S = Q K^T raw logits: (j_tiles=32, i_tiles=32, nb=4)
    qk_kernel<<<dim3(32, 32, NB), blk>>>();
    // row max / Z
    stats_kernel<<<dim3(L, NB), blk>>>();
    // att + residual epilogue: (i_tiles=32, c_tiles=2, nb=4)
    av_kernel<<<dim3(32, 2, NB), blk>>>(x, out, gamma);
}

// round 5
// speedup vs baseline: 1.0772x; 1.0772x over previous
#include <cuda_runtime.h>
#include <math.h>

#define NB 4
#define C 256
#define L 4096   // 64*64

// ---------------- scratch (__device__ globals: sanctioned alloc-free scratch) ----
__device__ float g_Qt[(size_t)NB * L * C];   // (n, i, c)  16.8 MB
__device__ float g_Kt[(size_t)NB * L * C];
__device__ float g_Vt[(size_t)NB * L * C];
__device__ float g_S [(size_t)NB * L * L];   // raw logits (n, i, j)  268 MB
__device__ float g_M [NB * L];               // row max
__device__ float g_Z [NB * L];               // row sum of exp(s - m)

// Compute one 8-deep k-chunk from smem buffer `buf`, with register-fragment
// double buffering so the LDS for kk+1 overlaps the 64 FFMAs of kk.
#define COMPUTE_CHUNK()                                                         \
    {                                                                           \
        float (* __restrict__ Ac)[128] = As[buf];                               \
        float (* __restrict__ Bc)[128] = Bs[buf];                               \
        float a_[2][8], b_[2][8];                                               \
        *(float4*)&a_[0][0] = *(const float4*)&Ac[0][tm * 8];                   \
        *(float4*)&a_[0][4] = *(const float4*)&Ac[0][tm * 8 + 4];               \
        *(float4*)&b_[0][0] = *(const float4*)&Bc[0][tn * 8];                   \
        *(float4*)&b_[0][4] = *(const float4*)&Bc[0][tn * 8 + 4];               \
        _Pragma("unroll")                                                       \
        for (int kk = 0; kk < 8; kk++) {                                        \
            if (kk < 7) {                                                       \
                *(float4*)&a_[(kk+1)&1][0] = *(const float4*)&Ac[kk+1][tm * 8];     \
                *(float4*)&a_[(kk+1)&1][4] = *(const float4*)&Ac[kk+1][tm * 8 + 4]; \
                *(float4*)&b_[(kk+1)&1][0] = *(const float4*)&Bc[kk+1][tn * 8];     \
                *(float4*)&b_[(kk+1)&1][4] = *(const float4*)&Bc[kk+1][tn * 8 + 4]; \
            }                                                                   \
            _Pragma("unroll")                                                   \
            for (int di = 0; di < 8; di++)                                      \
                _Pragma("unroll")                                               \
                for (int dj = 0; dj < 8; dj++)                                  \
                    acc[di][dj] = fmaf(a_[kk&1][di], b_[kk&1][dj], acc[di][dj]); \
        }                                                                       \
    }

// ---------------------------------------------------------------------------
// Kernel 1: 1x1 conv (channel-mixing GEMM). grid.z = nb*3 + which.
// Out[i][o] = sum_c W[o][c] * x[n][c][i] + b[o], written (i, o) row-major.
// ---------------------------------------------------------------------------
__global__ __launch_bounds__(256, 2) void conv1x1_kernel(
    const float* __restrict__ x,
    const float* __restrict__ Wq, const float* __restrict__ bq,
    const float* __restrict__ Wk, const float* __restrict__ bk,
    const float* __restrict__ Wv, const float* __restrict__ bv)
{
    int which = blockIdx.z % 3;
    int nb    = blockIdx.z / 3;
    const float* W    = (which == 0) ? Wq : (which == 1) ? Wk : Wv;
    const float* bias = (which == 0) ? bq : (which == 1) ? bk : bv;
    float* Out = ((which == 0) ? g_Qt : (which == 1) ? g_Kt : g_Vt)
                 + (size_t)nb * L * C;
    const float* xb = x + (size_t)nb * C * L;

    int o0 = blockIdx.x * 128;   // 2 tiles over C
    int i0 = blockIdx.y * 128;   // 32 tiles over L

    __shared__ float As[2][8][128];  // [c][i]
    __shared__ float Bs[2][8][128];  // [c][o]

    int t  = threadIdx.x;
    int tm = t >> 4, tn = t & 15;

    int arow = t >> 5;            // c in chunk (0..7)
    int acol = (t & 31) * 4;      // i
    int brow = t >> 1;            // o (0..127)
    int bcol = (t & 1) * 4;       // c in chunk

    const float* xp = &xb[(size_t)arow * L + i0 + acol];
    const float* wp = &W[(size_t)(o0 + brow) * C + bcol];

    float acc[8][8] = {};

    // prologue: chunk 0 into buffer 0
    float4 xv = *(const float4*)xp;
    float4 bw = *(const float4*)wp;
    *(float4*)&As[0][arow][acol] = xv;
    Bs[0][bcol + 0][brow] = bw.x;
    Bs[0][bcol + 1][brow] = bw.y;
    Bs[0][bcol + 2][brow] = bw.z;
    Bs[0][bcol + 3][brow] = bw.w;
    __syncthreads();

    int buf = 0;
    for (int kc = 0; kc < C; kc += 8) {
        bool more = (kc + 8 < C);
        if (more) {
            xv = *(const float4*)(xp + (size_t)(kc + 8) * L);
            bw = *(const float4*)(wp + kc + 8);
        }
        COMPUTE_CHUNK();
        if (more) {
            int nx = buf ^ 1;
            *(float4*)&As[nx][arow][acol] = xv;
            Bs[nx][bcol + 0][brow] = bw.x;
            Bs[nx][bcol + 1][brow] = bw.y;
            Bs[nx][bcol + 2][brow] = bw.z;
            Bs[nx][bcol + 3][brow] = bw.w;
            __syncthreads();
            buf = nx;
        }
    }

    #pragma unroll
    for (int di = 0; di < 8; di++) {
        int i = i0 + tm * 8 + di;
        #pragma unroll
        for (int dj = 0; dj < 8; dj += 4) {
            int o = o0 + tn * 8 + dj;
            float4 v;
            v.x = acc[di][dj + 0] + bias[o + 0];
            v.y = acc[di][dj + 1] + bias[o + 1];
            v.z = acc[di][dj + 2] + bias[o + 2];
            v.w = acc[di][dj + 3] + bias[o + 3];
            *(float4*)&Out[(size_t)i * C + o] = v;
        }
    }
}

// ---------------------------------------------------------------------------
// Kernel 2: S[i][j] = sum_c Q[i][c] * K[j][c]  (raw logits to global scratch)
// ---------------------------------------------------------------------------
__global__ __launch_bounds__(256, 2) void qk_kernel()
{
    int nb = blockIdx.z;
    int j0 = blockIdx.x * 128;
    int i0 = blockIdx.y * 128;
    const float* Q  = g_Qt + (size_t)nb * L * C;
    const float* Kt = g_Kt + (size_t)nb * L * C;

    __shared__ float As[2][8][128];  // [c][i]
    __shared__ float Bs[2][8][128];  // [c][j]

    int t  = threadIdx.x;
    int tm = t >> 4, tn = t & 15;
    int lrow = t >> 1;            // 0..127
    int lc   = (t & 1) * 4;       // 0 or 4

    const float* qp = &Q [(size_t)(i0 + lrow) * C + lc];
    const float* kp = &Kt[(size_t)(j0 + lrow) * C + lc];

    float acc[8][8] = {};

    float4 qa = *(const float4*)qp;
    float4 kb = *(const float4*)kp;
    As[0][lc + 0][lrow] = qa.x; As[0][lc + 1][lrow] = qa.y;
    As[0][lc + 2][lrow] = qa.z; As[0][lc + 3][lrow] = qa.w;
    Bs[0][lc + 0][lrow] = kb.x; Bs[0][lc + 1][lrow] = kb.y;
    Bs[0][lc + 2][lrow] = kb.z; Bs[0][lc + 3][lrow] = kb.w;
    __syncthreads();

    int buf = 0;
    for (int kc = 0; kc < C; kc += 8) {
        bool more = (kc + 8 < C);
        if (more) {
            qa = *(const float4*)(qp + kc + 8);
            kb = *(const float4*)(kp + kc + 8);
        }
        COMPUTE_CHUNK();
        if (more) {
            int nx = buf ^ 1;
            As[nx][lc + 0][lrow] = qa.x; As[nx][lc + 1][lrow] = qa.y;
            As[nx][lc + 2][lrow] = qa.z; As[nx][lc + 3][lrow] = qa.w;
            Bs[nx][lc + 0][lrow] = kb.x; Bs[nx][lc + 1][lrow] = kb.y;
            Bs[nx][lc + 2][lrow] = kb.z; Bs[nx][lc + 3][lrow] = kb.w;
            __syncthreads();
            buf = nx;
        }
    }

    float* Sp = g_S + (size_t)nb * L * L;
    #pragma unroll
    for (int di = 0; di < 8; di++) {
        size_t ro = (size_t)(i0 + tm * 8 + di) * L + j0 + tn * 8;
        *(float4*)&Sp[ro]     = make_float4(acc[di][0], acc[di][1], acc[di][2], acc[di][3]);
        *(float4*)&Sp[ro + 4] = make_float4(acc[di][4], acc[di][5], acc[di][6], acc[di][7]);
    }
}

// ---------------------------------------------------------------------------
// Kernel 3: per-row max and sum of exp(s - max). One block per (row, batch).
// ---------------------------------------------------------------------------
__global__ __launch_bounds__(256) void stats_kernel()
{
    int i  = blockIdx.x;
    int nb = blockIdx.y;
    const float* row = g_S + (size_t)nb * L * L + (size_t)i * L;
    __shared__ float red[256];
    int t = threadIdx.x;

    float vals[16];
    float m = -3.4e38f;
    #pragma unroll
    for (int r = 0; r < 16; r++) {
        vals[r] = row[t + r * 256];
        m = fmaxf(m, vals[r]);
    }
    red[t] = m;
    __syncthreads();
    for (int s = 128; s > 0; s >>= 1) {
        if (t < s) red[t] = fmaxf(red[t], red[t + s]);
        __syncthreads();
    }
    m = red[0];
    __syncthreads();

    float z = 0.0f;
    #pragma unroll
    for (int r = 0; r < 16; r++) z += __expf(vals[r] - m);
    red[t] = z;
    __syncthreads();
    for (int s = 128; s > 0; s >>= 1) {
        if (t < s) red[t] += red[t + s];
        __syncthreads();
    }
    if (t == 0) { g_M[nb * L + i] = m; g_Z[nb * L + i] = red[0]; }
}

// ---------------------------------------------------------------------------
// Kernel 4: att[c][i] = sum_j exp(S[i][j]-m_i) * V[j][c];
//           out[n][c][i] = x + gamma * att / Z_i
// ---------------------------------------------------------------------------
__global__ __launch_bounds__(256, 2) void av_kernel(
    const float* __restrict__ x, float* __restrict__ out,
    const float* __restrict__ gamma_p)
{
    int nb = blockIdx.z;
    int i0 = blockIdx.x * 128;   // 32 tiles
    int c0 = blockIdx.y * 128;   // 2 tiles
    const float* Sp = g_S  + (size_t)nb * L * L;
    const float* V  = g_Vt + (size_t)nb * L * C;

    __shared__ float As[2][8][128];  // [j][c]   (V, natural layout)
    __shared__ float Bs[2][8][128];  // [j][i]   (P = exp(S-m), transpose on store)
    __shared__ float Ms[128];
    __shared__ float Zs[128];

    int t  = threadIdx.x;
    int tm = t >> 4, tn = t & 15;
    int lrow = t >> 1;            // i local
    int lc   = (t & 1) * 4;       // j in chunk
    int arow = t >> 5;            // j in chunk (0..7)
    int acol = (t & 31) * 4;      // c

    if (t < 128) {
        Ms[t] = g_M[nb * L + i0 + t];
        Zs[t] = g_Z[nb * L + i0 + t];
    }
    __syncthreads();
    float mrow = Ms[lrow];

    const float* sp = &Sp[(size_t)(i0 + lrow) * L + lc];
    const float* vp = &V [(size_t)arow * C + c0 + acol];

    float acc[8][8] = {};

    float4 pa = *(const float4*)sp;
    float4 va = *(const float4*)vp;
    *(float4*)&As[0][arow][acol] = va;
    Bs[0][lc + 0][lrow] = __expf(pa.x - mrow);
    Bs[0][lc + 1][lrow] = __expf(pa.y - mrow);
    Bs[0][lc + 2][lrow] = __expf(pa.z - mrow);
    Bs[0][lc + 3][lrow] = __expf(pa.w - mrow);
    __syncthreads();

    int buf = 0;
    for (int jk = 0; jk < L; jk += 8) {
        bool more = (jk + 8 < L);
        if (more) {
            pa = *(const float4*)(sp + jk + 8);
            va = *(const float4*)(vp + (size_t)(jk + 8) * C);
        }
        COMPUTE_CHUNK();
        if (more) {
            int nx = buf ^ 1;
            *(float4*)&As[nx][arow][acol] = va;
            Bs[nx][lc + 0][lrow] = __expf(pa.x - mrow);
            Bs[nx][lc + 1][lrow] = __expf(pa.y - mrow);
            Bs[nx][lc + 2][lrow] = __expf(pa.z - mrow);
            Bs[nx][lc + 3][lrow] = __expf(pa.w - mrow);
            __syncthreads();
            buf = nx;
        }
    }

    float gamma = gamma_p[0];
    float zinv[8];
    #pragma unroll
    for (int dj = 0; dj < 8; dj++) zinv[dj] = gamma / Zs[tn * 8 + dj];

    #pragma unroll
    for (int di = 0; di < 8; di++) {
        int c = c0 + tm * 8 + di;
        size_t ro = ((size_t)nb * C + c) * L + i0 + tn * 8;
        #pragma unroll
        for (int dj = 0; dj < 8; dj += 4) {
            float4 xv = *(const float4*)&x[ro + dj];
            float4 ov;
            ov.x = xv.x + acc[di][dj + 0] * zinv[dj + 0];
            ov.y = xv.y + acc[di][dj + 1] * zinv[dj + 1];
            ov.z = xv.z + acc[di][dj + 2] * zinv[dj + 2];
            ov.w = xv.w + acc[di][dj + 3] * zinv[dj + 3];
            *(float4*)&out[ro + dj] = ov;
        }
    }
}

// ---------------------------------------------------------------------------
extern "C" void kernel_launch(void* const* d_in, const int* in_sizes, int n_in,
                              void* d_out, int out_size)
{
    const float* x     = (const float*)d_in[0];
    const float* Wq    = (const float*)d_in[1];
    const float* bq    = (const float*)d_in[2];
    const float* Wk    = (const float*)d_in[3];
    const float* bk    = (const float*)d_in[4];
    const float* Wv    = (const float*)d_in[5];
    const float* bv    = (const float*)d_in[6];
    const float* gamma = (const float*)d_in[7];
    float* out = (float*)d_out;

    dim3 blk(256);
    conv1x1_kernel<<<dim3(2, 32, NB * 3), blk>>>(x, Wq, bq, Wk, bk, Wv, bv);
    qk_kernel<<<dim3(32, 32, NB), blk>>>();
    stats_kernel<<<dim3(L, NB), blk>>>();
    av_kernel<<<dim3(32, 2, NB), blk>>>(x, out, gamma);
}

// round 8
// speedup vs baseline: 2.3739x; 2.2037x over previous
#include <cuda_runtime.h>
#include <cuda_bf16.h>
#include <math.h>
#include <stdint.h>

#define NB 4
#define C 256
#define L 4096   // 64*64

// ---------------- scratch (__device__ globals: sanctioned alloc-free scratch) ----
__device__ float g_Qt[(size_t)NB * L * C];   // (n, i, c) fp32
__device__ float g_Kt[(size_t)NB * L * C];
__device__ float g_Vt[(size_t)NB * L * C];
__device__ float g_S [(size_t)NB * L * L];   // raw logits fp32 (n, i, j)
__device__ float g_M [NB * L];
__device__ float g_Z [NB * L];
__device__ __nv_bfloat16 g_Qhi[(size_t)NB * L * C];  // (n, i, c)
__device__ __nv_bfloat16 g_Qlo[(size_t)NB * L * C];
__device__ __nv_bfloat16 g_Khi[(size_t)NB * L * C];
__device__ __nv_bfloat16 g_Klo[(size_t)NB * L * C];
__device__ __nv_bfloat16 g_Vhi[(size_t)NB * C * L];  // (n, c, i)  transposed
__device__ __nv_bfloat16 g_Vlo[(size_t)NB * C * L];
__device__ __nv_bfloat16 g_Phi[(size_t)NB * L * L];  // (n, i, j)
__device__ __nv_bfloat16 g_Plo[(size_t)NB * L * L];

// ======================= helpers ==========
__device__ __forceinline__ uint32_t smem_u32(const void* p) {
    uint32_t a;
    asm("{ .reg .u64 t; cvta.to.shared.u64 t, %1; cvt.u32.u64 %0, t; }" : "=r"(a) : "l"(p));
    return a;
}
#define CP_ASYNC16(dst, src) \
    asm volatile("cp.async.cg.shared.global [%0], [%1], 16;" :: "r"(dst), "l"(src))
#define CP_COMMIT() asm volatile("cp.async.commit_group;" ::: "memory")
#define CP_WAIT1()  asm volatile("cp.async.wait_group 1;" ::: "memory")
#define CP_WAIT0()  asm volatile("cp.async.wait_group 0;" ::: "memory")

// smem tile layout: 2 buffers, each {A:16KB, B:16KB}. Rows = 128B, SW128 swizzle.
// buf b: A at b*32768, B at b*32768 + 16384. (64KB total; +512B Zs in PV.)

__device__ __forceinline__ void load_chunk_pair(
    uint32_t smbase, int b,
    const char* Ag, long a_stride, const char* Bg, long b_stride,
    long colb, int lrow0, int lgran, int lsrcg)
{
    uint32_t da = smbase + b * 32768;
    uint32_t db = da + 16384;
    #pragma unroll
    for (int u = 0; u < 4; u++) {
        int row = lrow0 + u * 32;
        uint32_t doff = (uint32_t)row * 128 + lgran;
        CP_ASYNC16(da + doff, Ag + (long)row * a_stride + colb + lsrcg);
        CP_ASYNC16(db + doff, Bg + (long)row * b_stride + colb + lsrcg);
    }
    CP_COMMIT();
}

// ---------------------------------------------------------------------------
// HMMA mainloop: acc[2][8][4] += A(128 x K) * B(128 x K)^T over nch chunks of
// 64 bf16 k-values. Segment s of the 3-segment split selected by cc>>seg_shift.
// 8 warps: wm = wid&3 (M 32-blocks), wn = wid>>2 (N 64-blocks).
// ---------------------------------------------------------------------------
__device__ __forceinline__ void hmma_mainloop(
    uint32_t smbase, float (&acc)[2][8][4],
    const char* A0, const char* A1, const char* A2, long a_stride,
    const char* B0, const char* B1, const char* B2, long b_stride,
    int nch, int seg_shift)
{
    const int t = threadIdx.x;
    const int lane = t & 31, wid = t >> 5;
    const int wm = wid & 3, wn = wid >> 2;
    const char* Asg[3] = {A0, A1, A2};
    const char* Bsg[3] = {B0, B1, B2};
    const int mask = (1 << seg_shift) - 1;

    // cp.async per-thread constants
    const int lrow0 = t >> 3;
    const int lgran = ((t & 7) ^ ((t >> 3) & 7)) * 16;
    const int lsrcg = (t & 7) * 16;

    // ldmatrix per-lane constants
    const int a_row = wm * 32 + (lane & 7) + ((lane >> 3) & 1) * 8;
    const uint32_t a_x   = (uint32_t)((a_row & 7) * 16);
    const uint32_t a_c16 = (uint32_t)((lane >> 4) * 16);
    const int b_row = wn * 64 + (lane & 7) + ((lane >> 4) & 1) * 8;
    const uint32_t b_x   = (uint32_t)((b_row & 7) * 16);
    const uint32_t b_c16 = (uint32_t)(((lane >> 3) & 1) * 16);

    // prologue: chunk 0 -> buffer 0
    load_chunk_pair(smbase, 0, Asg[0], a_stride, Bsg[0], b_stride,
                    0, lrow0, lgran, lsrcg);

    for (int cc = 0; cc < nch; cc++) {
        int b = cc & 1;
        if (cc + 1 < nch) {
            int nc = cc + 1;
            int seg = nc >> seg_shift;
            long colb = (long)(nc & mask) * 128;
            load_chunk_pair(smbase, b ^ 1, Asg[seg], a_stride, Bsg[seg], b_stride,
                            colb, lrow0, lgran, lsrcg);
            CP_WAIT1();
        } else {
            CP_WAIT0();
        }
        __syncthreads();

        uint32_t Ab = smbase + b * 32768;
        uint32_t Bb = Ab + 16384;
        #pragma unroll
        for (int ks = 0; ks < 4; ks++) {
            uint32_t a[2][4];
            #pragma unroll
            for (int mi = 0; mi < 2; mi++) {
                uint32_t ad = Ab + (uint32_t)(a_row + mi * 16) * 128
                                 + (((uint32_t)(ks * 32) + a_c16) ^ a_x);
                asm volatile("ldmatrix.sync.aligned.m8n8.x4.shared.b16 {%0,%1,%2,%3}, [%4];"
                    : "=r"(a[mi][0]), "=r"(a[mi][1]), "=r"(a[mi][2]), "=r"(a[mi][3])
                    : "r"(ad));
            }
            uint32_t bb[4][4];
            #pragma unroll
            for (int np = 0; np < 4; np++) {
                uint32_t bd = Bb + (uint32_t)(b_row + np * 16) * 128
                                 + (((uint32_t)(ks * 32) + b_c16) ^ b_x);
                asm volatile("ldmatrix.sync.aligned.m8n8.x4.shared.b16 {%0,%1,%2,%3}, [%4];"
                    : "=r"(bb[np][0]), "=r"(bb[np][1]), "=r"(bb[np][2]), "=r"(bb[np][3])
                    : "r"(bd));
            }
            #pragma unroll
            for (int mi = 0; mi < 2; mi++)
                #pragma unroll
                for (int nf = 0; nf < 8; nf++) {
                    asm volatile(
                        "mma.sync.aligned.m16n8k16.row.col.f32.bf16.bf16.f32 "
                        "{%0,%1,%2,%3}, {%4,%5,%6,%7}, {%8,%9}, {%0,%1,%2,%3};"
                        : "+f"(acc[mi][nf][0]), "+f"(acc[mi][nf][1]),
                          "+f"(acc[mi][nf][2]), "+f"(acc[mi][nf][3])
                        : "r"(a[mi][0]), "r"(a[mi][1]), "r"(a[mi][2]), "r"(a[mi][3]),
                          "r"(bb[nf >> 1][(nf & 1) * 2 + 0]),
                          "r"(bb[nf >> 1][(nf & 1) * 2 + 1]));
                }
        }
        __syncthreads();   // protect buffer b before it is reloaded (cc+2)
    }
}

// ---------------------------------------------------------------------------
// QK^T logits: S[i][j] = hiQ.hiK + hiQ.loK + loQ.hiK, K = 3*256.
// ---------------------------------------------------------------------------
__global__ __launch_bounds__(256) void qk_hmma_kernel()
{
    extern __shared__ char sm[];
    uint32_t smbase = smem_u32(sm);
    int nb = blockIdx.z, j0 = blockIdx.x * 128, i0 = blockIdx.y * 128;
    int lane = threadIdx.x & 31, wid = threadIdx.x >> 5;
    int wm = wid & 3, wn = wid >> 2;

    size_t ra = ((size_t)nb * L + i0) * C;
    size_t rb = ((size_t)nb * L + j0) * C;

    float acc[2][8][4] = {};
    hmma_mainloop(smbase, acc,
        (const char*)(g_Qhi + ra), (const char*)(g_Qhi + ra), (const char*)(g_Qlo + ra), (long)C * 2,
        (const char*)(g_Khi + rb), (const char*)(g_Klo + rb), (const char*)(g_Khi + rb), (long)C * 2,
        12, 2);

    float* Sp = g_S + (size_t)nb * L * L;
    int r0 = i0 + wm * 32 + (lane >> 2);
    int cb = j0 + wn * 64 + (lane & 3) * 2;
    #pragma unroll
    for (int mi = 0; mi < 2; mi++)
        #pragma unroll
        for (int nf = 0; nf < 8; nf++) {
            int row = r0 + mi * 16;
            int col = cb + nf * 8;
            *(float2*)&Sp[(size_t)row * L + col] = make_float2(acc[mi][nf][0], acc[mi][nf][1]);
            *(float2*)&Sp[(size_t)(row + 8) * L + col] = make_float2(acc[mi][nf][2], acc[mi][nf][3]);
        }
}

// ---------------------------------------------------------------------------
// P.V: C[c][i] = sum_j V'[c][j] P[i][j]; split: hiV.hiP + hiV.loP + loV.hiP.
// Epilogue: out[n,c,i] = x + gamma * C / Z_i (coalesced along i).
// ---------------------------------------------------------------------------
__global__ __launch_bounds__(256) void av_hmma_kernel(
    const float* __restrict__ x, float* __restrict__ out,
    const float* __restrict__ gamma_p)
{
    extern __shared__ char sm[];
    uint32_t smbase = smem_u32(sm);
    float* Zs = (float*)(sm + 65536);
    int nb = blockIdx.z, i0 = blockIdx.x * 128, c0 = blockIdx.y * 128;
    int t = threadIdx.x, lane = t & 31, wid = t >> 5;
    int wm = wid & 3, wn = wid >> 2;

    if (t < 128) Zs[t] = gamma_p[0] / g_Z[nb * L + i0 + t];
    // no explicit sync needed before mainloop's first __syncthreads (Zs read at end)

    size_t ra = ((size_t)nb * C + c0) * L;   // V' rows (c, j)
    size_t rb = ((size_t)nb * L + i0) * L;   // P rows (i, j)

    float acc[2][8][4] = {};
    hmma_mainloop(smbase, acc,
        (const char*)(g_Vhi + ra), (const char*)(g_Vhi + ra), (const char*)(g_Vlo + ra), (long)L * 2,
        (const char*)(g_Phi + rb), (const char*)(g_Plo + rb), (const char*)(g_Phi + rb), (long)L * 2,
        192, 6);

    int r0 = c0 + wm * 32 + (lane >> 2);             // c
    int cl = wn * 64 + (lane & 3) * 2;               // i local
    #pragma unroll
    for (int mi = 0; mi < 2; mi++)
        #pragma unroll
        for (int nf = 0; nf < 8; nf++) {
            int c = r0 + mi * 16;
            int il = cl + nf * 8;
            float z0 = Zs[il], z1 = Zs[il + 1];
            size_t a0 = ((size_t)nb * C + c) * L + i0 + il;
            size_t a1 = ((size_t)nb * C + c + 8) * L + i0 + il;
            float2 x0 = *(const float2*)&x[a0];
            float2 x1 = *(const float2*)&x[a1];
            *(float2*)&out[a0] = make_float2(x0.x + acc[mi][nf][0] * z0,
                                             x0.y + acc[mi][nf][1] * z1);
            *(float2*)&out[a1] = make_float2(x1.x + acc[mi][nf][2] * z0,
                                             x1.y + acc[mi][nf][3] * z1);
        }
}

// ---------------------------------------------------------------------------
// Kernel 1: 1x1 conv (FFMA GEMM — unchanged; small share of runtime)
// ---------------------------------------------------------------------------
#define COMPUTE_CHUNK()                                                         \
    {                                                                           \
        float (* __restrict__ Ac)[128] = As[buf];                               \
        float (* __restrict__ Bc)[128] = Bs[buf];                               \
        float a_[2][8], b_[2][8];                                               \
        *(float4*)&a_[0][0] = *(const float4*)&Ac[0][tm * 8];                   \
        *(float4*)&a_[0][4] = *(const float4*)&Ac[0][tm * 8 + 4];               \
        *(float4*)&b_[0][0] = *(const float4*)&Bc[0][tn * 8];                   \
        *(float4*)&b_[0][4] = *(const float4*)&Bc[0][tn * 8 + 4];               \
        _Pragma("unroll")                                                       \
        for (int kk = 0; kk < 8; kk++) {                                        \
            if (kk < 7) {                                                       \
                *(float4*)&a_[(kk+1)&1][0] = *(const float4*)&Ac[kk+1][tm * 8];     \
                *(float4*)&a_[(kk+1)&1][4] = *(const float4*)&Ac[kk+1][tm * 8 + 4]; \
                *(float4*)&b_[(kk+1)&1][0] = *(const float4*)&Bc[kk+1][tn * 8];     \
                *(float4*)&b_[(kk+1)&1][4] = *(const float4*)&Bc[kk+1][tn * 8 + 4]; \
            }                                                                   \
            _Pragma("unroll")                                                   \
            for (int di = 0; di < 8; di++)                                      \
                _Pragma("unroll")                                               \
                for (int dj = 0; dj < 8; dj++)                                  \
                    acc[di][dj] = fmaf(a_[kk&1][di], b_[kk&1][dj], acc[di][dj]); \
        }                                                                       \
    }

__global__ __launch_bounds__(256, 2) void conv1x1_kernel(
    const float* __restrict__ x,
    const float* __restrict__ Wq, const float* __restrict__ bq,
    const float* __restrict__ Wk, const float* __restrict__ bk,
    const float* __restrict__ Wv, const float* __restrict__ bv)
{
    int which = blockIdx.z % 3;
    int nb    = blockIdx.z / 3;
    const float* W    = (which == 0) ? Wq : (which == 1) ? Wk : Wv;
    const float* bias = (which == 0) ? bq : (which == 1) ? bk : bv;
    float* Out = ((which == 0) ? g_Qt : (which == 1) ? g_Kt : g_Vt)
                 + (size_t)nb * L * C;
    const float* xb = x + (size_t)nb * C * L;

    int o0 = blockIdx.x * 128;
    int i0 = blockIdx.y * 128;

    __shared__ float As[2][8][128];
    __shared__ float Bs[2][8][128];

    int t  = threadIdx.x;
    int tm = t >> 4, tn = t & 15;
    int arow = t >> 5, acol = (t & 31) * 4;
    int brow = t >> 1, bcol = (t & 1) * 4;

    const float* xp = &xb[(size_t)arow * L + i0 + acol];
    const float* wp = &W[(size_t)(o0 + brow) * C + bcol];

    float acc[8][8] = {};

    float4 xv = *(const float4*)xp;
    float4 bw = *(const float4*)wp;
    *(float4*)&As[0][arow][acol] = xv;
    Bs[0][bcol + 0][brow] = bw.x; Bs[0][bcol + 1][brow] = bw.y;
    Bs[0][bcol + 2][brow] = bw.z; Bs[0][bcol + 3][brow] = bw.w;
    __syncthreads();

    int buf = 0;
    for (int kc = 0; kc < C; kc += 8) {
        bool more = (kc + 8 < C);
        if (more) {
            xv = *(const float4*)(xp + (size_t)(kc + 8) * L);
            bw = *(const float4*)(wp + kc + 8);
        }
        COMPUTE_CHUNK();
        if (more) {
            int nx = buf ^ 1;
            *(float4*)&As[nx][arow][acol] = xv;
            Bs[nx][bcol + 0][brow] = bw.x; Bs[nx][bcol + 1][brow] = bw.y;
            Bs[nx][bcol + 2][brow] = bw.z; Bs[nx][bcol + 3][brow] = bw.w;
            __syncthreads();
            buf = nx;
        }
    }

    #pragma unroll
    for (int di = 0; di < 8; di++) {
        int i = i0 + tm * 8 + di;
        #pragma unroll
        for (int dj = 0; dj < 8; dj += 4) {
            int o = o0 + tn * 8 + dj;
            float4 v;
            v.x = acc[di][dj + 0] + bias[o + 0];
            v.y = acc[di][dj + 1] + bias[o + 1];
            v.z = acc[di][dj + 2] + bias[o + 2];
            v.w = acc[di][dj + 3] + bias[o + 3];
            *(float4*)&Out[(size_t)i * C + o] = v;
        }
    }
}

// ---------------------------------------------------------------------------
// Split Q, K fp32 -> (hi, lo) bf16 (same (i,c) layout)
// ---------------------------------------------------------------------------
__global__ __launch_bounds__(256) void split_qk_kernel()
{
    size_t idx = (size_t)blockIdx.x * 1024 + threadIdx.x;
    #pragma unroll
    for (int k = 0; k < 4; k++) {
        size_t i = idx + (size_t)k * 256;
        float q = g_Qt[i];
        __nv_bfloat16 qh = __float2bfloat16(q);
        g_Qhi[i] = qh;
        g_Qlo[i] = __float2bfloat16(q - __bfloat162float(qh));
        float kv = g_Kt[i];
        __nv_bfloat16 kh = __float2bfloat16(kv);
        g_Khi[i] = kh;
        g_Klo[i] = __float2bfloat16(kv - __bfloat162float(kh));
    }
}

// ---------------------------------------------------------------------------
// V: transpose (i,c) -> (c,i) and split to bf16 hi/lo
// ---------------------------------------------------------------------------
__global__ __launch_bounds__(1024) void split_v_kernel()
{
    __shared__ float tile[32][33];
    int nb = blockIdx.z;
    int i0 = blockIdx.x * 32;
    int c0 = blockIdx.y * 32;
    int tx = threadIdx.x & 31, ty = threadIdx.x >> 5;
    const float* V = g_Vt + (size_t)nb * L * C;
    tile[ty][tx] = V[(size_t)(i0 + ty) * C + c0 + tx];
    __syncthreads();
    float v = tile[tx][ty];
    __nv_bfloat16 h = __float2bfloat16(v);
    size_t o = ((size_t)nb * C + c0 + ty) * L + i0 + tx;
    g_Vhi[o] = h;
    g_Vlo[o] = __float2bfloat16(v - __bfloat162float(h));
}

// ---------------------------------------------------------------------------
// Stats + P split fused: row max, Z, and exp(s-m) hi/lo bf16
// ---------------------------------------------------------------------------
__global__ __launch_bounds__(256) void stats_split_kernel()
{
    int i  = blockIdx.x;
    int nb = blockIdx.y;
    size_t rowoff = (size_t)nb * L * L + (size_t)i * L;
    const float* row = g_S + rowoff;
    __shared__ float red[256];
    int t = threadIdx.x;

    float vals[16];
    float m = -3.4e38f;
    #pragma unroll
    for (int r = 0; r < 16; r++) {
        vals[r] = row[t + r * 256];
        m = fmaxf(m, vals[r]);
    }
    red[t] = m;
    __syncthreads();
    for (int s = 128; s > 0; s >>= 1) {
        if (t < s) red[t] = fmaxf(red[t], red[t + s]);
        __syncthreads();
    }
    m = red[0];
    __syncthreads();

    float z = 0.0f;
    #pragma unroll
    for (int r = 0; r < 16; r++) {
        float e = __expf(vals[r] - m);
        z += e;
        __nv_bfloat16 h = __float2bfloat16(e);
        g_Phi[rowoff + t + r * 256] = h;
        g_Plo[rowoff + t + r * 256] = __float2bfloat16(e - __bfloat162float(h));
    }
    red[t] = z;
    __syncthreads();
    for (int s = 128; s > 0; s >>= 1) {
        if (t < s) red[t] += red[t + s];
        __syncthreads();
    }
    if (t == 0) { g_M[nb * L + i] = m; g_Z[nb * L + i] = red[0]; }
}

// ---------------------------------------------------------------------------
extern "C" void kernel_launch(void* const* d_in, const int* in_sizes, int n_in,
                              void* d_out, int out_size)
{
    const float* x     = (const float*)d_in[0];
    const float* Wq    = (const float*)d_in[1];
    const float* bq    = (const float*)d_in[2];
    const float* Wk    = (const float*)d_in[3];
    const float* bk    = (const float*)d_in[4];
    const float* Wv    = (const float*)d_in[5];
    const float* bv    = (const float*)d_in[6];
    const float* gamma = (const float*)d_in[7];
    float* out = (float*)d_out;

    cudaFuncSetAttribute(qk_hmma_kernel, cudaFuncAttributeMaxDynamicSharedMemorySize, 65536);
    cudaFuncSetAttribute(av_hmma_kernel, cudaFuncAttributeMaxDynamicSharedMemorySize, 66048);

    conv1x1_kernel<<<dim3(2, 32, NB * 3), 256>>>(x, Wq, bq, Wk, bk, Wv, bv);
    split_qk_kernel<<<dim3(NB * L * C / 1024), 256>>>();
    split_v_kernel<<<dim3(L / 32, C / 32, NB), 1024>>>();
    qk_hmma_kernel<<<dim3(32, 32, NB), 256, 65536>>>();
    stats_split_kernel<<<dim3(L, NB), 256>>>();
    av_hmma_kernel<<<dim3(32, 2, NB), 256, 66048>>>(x, out, gamma);
}